// round 13
// baseline (speedup 1.0000x reference)
#include <cuda_runtime.h>
#include <cstdint>

#define T_STEPS 1000
#define B       64
#define NIN     512
#define NOUT    128
#define KS      16      // i-slices (k-split of NIN)
#define OT      8       // o-tiles
#define OTS     16      // o per tile
#define ISW     32      // i per slice
#define NCTA    128     // KS * OT
#define TPB     256
#define NBAR    16      // distributed barrier counter lines
#define LRATE   1e-3f

// Persistent device state (no cudaMalloc allowed)
__device__ float g_psp[(size_t)T_STEPS * B * NIN];   // 131 MB precomputed PSP traces
__device__ float g_zin_part[KS * B * NOUT];          // per-k-slice z_in partials
__device__ float g_zout[B * NOUT];                   // current step softmax output
__device__ float g_bias[NOUT];
__device__ unsigned g_ctrs[NBAR][32];                // distributed barrier counters (128B apart)

__global__ void init_kernel(const float* __restrict__ bias) {
    int t = threadIdx.x;
    if (t < NOUT) g_bias[t] = bias[t];
    if (t < NBAR) g_ctrs[t][0] = 0u;
}

// PSP trace: independent scan over T for each (b, i) pair. 32768 threads.
__global__ void psp_kernel(const float* __restrict__ spikes) {
    int idx = blockIdx.x * blockDim.x + threadIdx.x;   // 0..32767
    float tr = 0.f;
    const float* sp = spikes + idx;
    float* pp = g_psp + idx;
#pragma unroll 4
    for (int t = 0; t < T_STEPS; t++) {
        tr = 0.9f * tr + sp[(size_t)t * (B * NIN)];
        pp[(size_t)t * (B * NIN)] = tr;
    }
}

// Distributed grid barrier. Same release/acquire + cumulativity-fence protocol
// as the proven R3 barrier, but arrivals are spread over NBAR=16 independent
// L2 lines (8 RMWs each instead of 128 on one line) and observed by 16
// parallel polling threads. Thread 0's post-observe __threadfence provides
// the SM-wide L1 invalidate (CCTL.IVALL) exactly as before.
__device__ __forceinline__ void grid_barrier(unsigned target, int cidx) {
    __syncthreads();
    if (threadIdx.x == 0) {
        __threadfence();   // release my CTA's prior writes (cumulative w/ bar.sync)
        asm volatile("red.release.gpu.add.u32 [%0], %1;"
                     :: "l"(&g_ctrs[cidx][0]), "r"(1u) : "memory");
    }
    if (threadIdx.x < NBAR) {
        unsigned v;
        do {
            asm volatile("ld.acquire.gpu.u32 %0, [%1];"
                         : "=r"(v) : "l"(&g_ctrs[threadIdx.x][0]) : "memory");
        } while (v < target);
    }
    __syncthreads();
    if (threadIdx.x == 0) __threadfence();   // acquire cumulativity: flush stale L1
    __syncthreads();
}

__global__ void __launch_bounds__(TPB, 1)
snn_kernel(const float* __restrict__ weight, float* __restrict__ out, int out_size) {
    __shared__ float sW[OTS][ISW + 4];   // this CTA's W slice (persistent, padded)
    __shared__ float sP[2][B][ISW];      // double-buffered psp slice (t and t-1)
    __shared__ float sZ[B][OTS];         // z_out columns for this o-tile
    __shared__ float sRed[8];            // softmax cross-warp scratch

    const int cta = blockIdx.x;
    const int tid = threadIdx.x;
    const int ot = cta & (OT - 1);       // o-tile id
    const int is = cta >> 3;             // i-slice id
    const int o0 = ot * OTS;
    const int i0 = is * ISW;
    const int cidx = cta & (NBAR - 1);   // this CTA's arrival counter

    // W slice lives in smem for the whole kernel.
    for (int idx = tid; idx < OTS * ISW; idx += TPB) {
        int ol = idx >> 5, il = idx & 31;
        sW[ol][il] = weight[(o0 + ol) * NIN + i0 + il];
    }

    const int olA = tid >> 4;            // STDP phase: o_local (0..15)
    const int iA  = (tid & 15) * 2;      // STDP phase: i pair
    const int olB = tid & 15;            // GEMM phase: o_local
    const int b0  = tid >> 4;            // GEMM phase: base batch row
    const bool wr_bias = (is == 0) && ((tid & 15) == 0);

    // psp smem-commit / prefetch geometry (512 float4 per slice, 2 per thread)
    const int pb0 = tid >> 3,          pc0 = (tid & 7) * 4;
    const int pb1 = (tid + TPB) >> 3,  pc1 = ((tid + TPB) & 7) * 4;

    // prefetch psp[0] into registers
    float4 pf0, pf1;
    {
        const float* src = g_psp + i0;
        pf0 = *(const float4*)&src[pb0 * NIN + pc0];
        pf1 = *(const float4*)&src[pb1 * NIN + pc1];
    }

    float u_reg = 0.f;                   // membrane u[cta][tid] (cta<64, tid<128)
    unsigned ep = 0;

    __syncthreads();

    for (int t = 0; t < T_STEPS; t++) {
        const int cur = t & 1;

        // ---- stage A: sZ load (z_out of t-1), commit prefetched psp[t],
        //               issue prefetch of psp[t+1] ----
        if (t > 0) {
            int b = tid >> 2, c4 = tid & 3;          // 256 float4 = 64x16 tile
            *(float4*)&sZ[b][c4 * 4] =
                *(const float4*)&g_zout[b * NOUT + o0 + c4 * 4];
        }
        *(float4*)&sP[cur][pb0][pc0] = pf0;
        *(float4*)&sP[cur][pb1][pc1] = pf1;
        if (t + 1 < T_STEPS) {
            const float* src = g_psp + (size_t)(t + 1) * (B * NIN) + i0;
            pf0 = *(const float4*)&src[pb0 * NIN + pc0];
            pf1 = *(const float4*)&src[pb1 * NIN + pc1];
        }
        __syncthreads();

        // ---- stage B: Nessler STDP update of this CTA's W slice (uses step t-1) ----
        if (t > 0) {
            const float* P = &sP[cur ^ 1][0][0];     // psp of step t-1
            float acc0 = 0.f, acc1 = 0.f, pm = 0.f;
#pragma unroll 8
            for (int b = 0; b < B; b++) {
                float z = sZ[b][olA];
                pm += z;
                float2 p = *(const float2*)&P[b * ISW + iA];
                acc0 += z * p.x;
                acc1 += z * p.y;
            }
            pm *= (1.f / B);
            float w0 = sW[olA][iA], w1 = sW[olA][iA + 1];
            w0 += LRATE * (__expf(-w0) * acc0 * (1.f / B) - pm);
            w1 += LRATE * (__expf(-w1) * acc1 * (1.f / B) - pm);
            sW[olA][iA]     = w0;
            sW[olA][iA + 1] = w1;
            if (wr_bias) {
                float bb = g_bias[o0 + olA];
                g_bias[o0 + olA] = bb + LRATE * (__expf(-bb) - 1.f) * pm;
            }
        }
        __syncthreads();

        // ---- stage C: z_in partials for this (o-tile, k-slice) ----
        {
            const float* P = &sP[cur][0][0];
            float4 w[8];
#pragma unroll
            for (int q = 0; q < 8; q++) w[q] = *(const float4*)&sW[olB][q * 4];
#pragma unroll
            for (int j = 0; j < 4; j++) {
                int b = b0 + j * 16;
                const float* pr = &P[b * ISW];
                float acc = 0.f;
#pragma unroll
                for (int q = 0; q < 8; q++) {
                    float4 p = *(const float4*)&pr[q * 4];
                    acc += p.x * w[q].x; acc += p.y * w[q].y;
                    acc += p.z * w[q].z; acc += p.w * w[q].w;
                }
                g_zin_part[(is * B + b) * NOUT + o0 + olB] = acc;
            }
        }
        grid_barrier(++ep * (NCTA / NBAR), cidx);

        // ---- stage D: reduce partials, membrane, softmax (CTA b = 0..63) ----
        if (cta < B) {
            float e = 0.f;
            if (tid < NOUT) {
                float z = g_bias[tid];
#pragma unroll
                for (int s = 0; s < KS; s++)
                    z += g_zin_part[(s * B + cta) * NOUT + tid];
                u_reg = 0.9f * u_reg + z;
                float m = u_reg;
#pragma unroll
                for (int o = 16; o > 0; o >>= 1)
                    m = fmaxf(m, __shfl_xor_sync(0xffffffffu, m, o));
                if ((tid & 31) == 0) sRed[tid >> 5] = m;
            }
            __syncthreads();
            float mx = fmaxf(fmaxf(sRed[0], sRed[1]), fmaxf(sRed[2], sRed[3]));
            if (tid < NOUT) {
                e = __expf(u_reg - mx);
                float s = e;
#pragma unroll
                for (int o = 16; o > 0; o >>= 1)
                    s += __shfl_xor_sync(0xffffffffu, s, o);
                if ((tid & 31) == 0) sRed[4 + (tid >> 5)] = s;
            }
            __syncthreads();
            if (tid < NOUT) {
                float z = e / (sRed[4] + sRed[5] + sRed[6] + sRed[7]);
                g_zout[cta * NOUT + tid] = z;
                out[(size_t)t * (B * NOUT) + cta * NOUT + tid] = z;
                if (t == T_STEPS - 1 && out_size >= (T_STEPS + 1) * B * NOUT)
                    out[(size_t)T_STEPS * (B * NOUT) + cta * NOUT + tid] = u_reg;
            }
        }
        grid_barrier(++ep * (NCTA / NBAR), cidx);
    }
}

extern "C" void kernel_launch(void* const* d_in, const int* in_sizes, int n_in,
                              void* d_out, int out_size) {
    const float* spikes = nullptr;
    const float* weight = nullptr;
    const float* bias   = nullptr;
    for (int i = 0; i < n_in; i++) {
        long n = in_sizes[i];
        if      (n == (long)T_STEPS * B * NIN) spikes = (const float*)d_in[i];
        else if (n == (long)NOUT * NIN)        weight = (const float*)d_in[i];
        else if (n == (long)NOUT)              bias   = (const float*)d_in[i];
    }
    init_kernel<<<1, 128>>>(bias);
    psp_kernel<<<64, 512>>>(spikes);
    snn_kernel<<<NCTA, TPB>>>(weight, (float*)d_out, out_size);
}